// round 8
// baseline (speedup 1.0000x reference)
#include <cuda_runtime.h>
#include <math.h>
#include <stdint.h>

#define SCALEF 0.70710678118654752440f
typedef unsigned long long u64;

// ---------------- f32x2 helpers ----------------
__device__ __forceinline__ u64 dup_f(float x){ u64 r; asm("mov.b64 %0,{%1,%1};" : "=l"(r) : "f"(x)); return r; }
__device__ __forceinline__ u64 pack2(float lo, float hi){ u64 r; asm("mov.b64 %0,{%1,%2};" : "=l"(r) : "f"(lo), "f"(hi)); return r; }
__device__ __forceinline__ u64 fma2(u64 a, u64 b, u64 c){ u64 d; asm("fma.rn.f32x2 %0,%1,%2,%3;" : "=l"(d) : "l"(a),"l"(b),"l"(c)); return d; }
__device__ __forceinline__ float lo_f(u64 x){ float a,b; asm("mov.b64 {%0,%1},%2;" : "=f"(a),"=f"(b) : "l"(x)); return a; }
__device__ __forceinline__ float hi_f(u64 x){ float a,b; asm("mov.b64 {%0,%1},%2;" : "=f"(a),"=f"(b) : "l"(x)); return b; }
__device__ __forceinline__ float to_tf32(float x){ float r; asm("cvt.rna.tf32.f32 %0, %1;" : "=f"(r) : "f"(x)); return r; }

// legacy tensor-core MMA: D(16x8) += A(16x8) * B(8x8), tf32 inputs, f32 accum
__device__ __forceinline__ void mma_tf32(float* c, uint32_t a0, uint32_t a1, uint32_t a2, uint32_t a3,
                                         uint32_t b0, uint32_t b1)
{
    asm volatile(
        "mma.sync.aligned.m16n8k8.row.col.f32.tf32.tf32.f32 "
        "{%0,%1,%2,%3}, {%4,%5,%6,%7}, {%8,%9}, {%0,%1,%2,%3};"
        : "+f"(c[0]), "+f"(c[1]), "+f"(c[2]), "+f"(c[3])
        : "r"(a0), "r"(a1), "r"(a2), "r"(a3), "r"(b0), "r"(b1));
}

// ---------------- scratch ----------------
__device__ float g_vecH[4*64*256];     // tf32-hi of a^v tables  [m][v][hn]
__device__ float g_vecL[4*64*256];     // tf32-lo residual
__device__ float g_vB[2*256];          // sigmoid(B1), sigmoid(B2)
__device__ float g_c1[256];
__device__ float g_c2[256];
__device__ float g_outs[2*1024*256];   // [dir][l][hn]
__device__ float g_kk[128*1024];       // conv kernel [h][l], boundary-scaled
__device__ float g_Kf[32*63*64];       // combined corr kernel [c][dqi][dpi pad64]
__device__ u64   g_xt2[32*4*64*64];    // x, b-pair packed
__device__ u64   g_yt2[32*4*64*64];    // conv output

// ---------------- kernel A: build vec tables (tf32 hi/lo split) ----------------
__global__ void k_vec(const float* __restrict__ A1, const float* __restrict__ A2,
                      const float* __restrict__ A3, const float* __restrict__ A4,
                      const float* __restrict__ B1, const float* __restrict__ B2,
                      const float* __restrict__ C1, const float* __restrict__ C2)
{
    int idx = blockIdx.x * 256 + threadIdx.x;   // 65536 = 4m * 64v * 256hn
    int t = idx & 255;
    int v = (idx >> 8) & 63;
    int m = idx >> 14;
    const float* As[4] = {A1, A2, A3, A4};
    float a = 1.0f / (1.0f + expf(-As[m][t]));
    float p = (v == 0) ? 1.0f : exp2f((float)v * log2f(a));
    float h = to_tf32(p);
    g_vecH[idx] = h;
    g_vecL[idx] = to_tf32(p - h);
    if (idx < 256) {
        g_vB[t]       = 1.0f / (1.0f + expf(-B1[t]));
        g_vB[256 + t] = 1.0f / (1.0f + expf(-B2[t]));
        g_c1[t] = C1[t] * SCALEF;
        g_c2[t] = C2[t] * SCALEF;
    }
}

// ---------------- kernel B: legacy-MMA GEMM-product + segment reduction ----------------
// block = (q, l, dir). Tile: 64 rows (= one l segment) x 64 hn x K=64.
// 8 warps = 4 row-groups(16 rows) x 2 hn-groups(32). 4 accumulator sets (one per A-matrix),
// each built with 3xTF32 (Ah*Bh + Ah*Bl + Al*Bh). Epilogue: elementwise product of the 4
// + B-term, reduce over 64 rows -> g_outs[dir][l][q*64 + 0..63].
#define PRODP 68   // uint2 pitch (row of 64 + pad)
__global__ __launch_bounds__(256, 2) void k_prod_m(
    const float* __restrict__ M1, const float* __restrict__ M2,
    const float* __restrict__ M3, const float* __restrict__ M4,
    const float* __restrict__ MB,
    const float* __restrict__ N1, const float* __restrict__ N2,
    const float* __restrict__ N3, const float* __restrict__ N4,
    const float* __restrict__ NB)
{
    extern __shared__ char smc[];
    uint2* sA   = (uint2*)smc;                         // [64][PRODP]  (hi,lo) of M rows
    uint2* sB   = (uint2*)(smc + 64*PRODP*8);          // [64 n][PRODP k] (hi,lo) of vec
    float* svB0 = (float*)(smc + 2*64*PRODP*8);        // 64
    float* svB1 = svB0 + 64;                           // 64
    float* sRed = svB1 + 64;                           // [4][64]

    int q   = blockIdx.x;   // hn quarter 0..3
    int l   = blockIdx.y;   // 0..1023
    int dir = blockIdx.z;   // 0..1
    const float* Mlist[4];
    const float* MBp;
    if (dir == 0) { Mlist[0]=M1; Mlist[1]=M2; Mlist[2]=M3; Mlist[3]=M4; MBp=MB; }
    else          { Mlist[0]=N1; Mlist[1]=N2; Mlist[2]=N3; Mlist[3]=N4; MBp=NB; }

    int tid  = threadIdx.x;
    int wid  = tid >> 5;
    int lane = tid & 31;
    int rowg = wid >> 1;          // 0..3  (16-row group)
    int hng  = wid & 1;           // 0..1  (32-col group)
    int lr   = lane >> 2;         // 0..7  (groupID)
    int lc   = lane & 3;          // 0..3  (threadID-in-group)

    if (tid < 64) {
        svB0[tid] = g_vB[q*64 + tid];
        svB1[tid] = g_vB[256 + q*64 + tid];
    }

    float acc[4][4][4];   // [m][ntile][frag]
    #pragma unroll
    for (int m = 0; m < 4; m++)
        #pragma unroll
        for (int t = 0; t < 4; t++)
            #pragma unroll
            for (int i = 0; i < 4; i++) acc[m][t][i] = 0.0f;

    for (int m = 0; m < 4; m++) {
        __syncthreads();   // protect smem from previous iteration's readers
        const float* Mg = Mlist[m] + (size_t)l * 4096;
        for (int idx = tid; idx < 4096; idx += 256) {
            int row = idx >> 6, k = idx & 63;
            float x = Mg[idx];
            float h = to_tf32(x);
            float lo = to_tf32(x - h);
            sA[row*PRODP + k] = make_uint2(__float_as_uint(h), __float_as_uint(lo));
        }
        const float* VH = g_vecH + m*16384 + q*64;
        const float* VL = g_vecL + m*16384 + q*64;
        for (int idx = tid; idx < 4096; idx += 256) {
            int n = idx & 63, k = idx >> 6;
            sB[n*PRODP + k] = make_uint2(__float_as_uint(VH[k*256 + n]),
                                         __float_as_uint(VL[k*256 + n]));
        }
        __syncthreads();

        int r0 = rowg*16 + lr;
        #pragma unroll
        for (int ks = 0; ks < 8; ks++) {
            int k0 = ks*8 + lc;
            uint2 A0 = sA[ r0      *PRODP + k0];
            uint2 A1 = sA[(r0 + 8) *PRODP + k0];
            uint2 A2 = sA[ r0      *PRODP + k0 + 4];
            uint2 A3 = sA[(r0 + 8) *PRODP + k0 + 4];
            #pragma unroll
            for (int t = 0; t < 4; t++) {
                int nb = hng*32 + t*8 + lr;
                uint2 B0 = sB[nb*PRODP + k0];
                uint2 B1 = sB[nb*PRODP + k0 + 4];
                mma_tf32(acc[m][t], A0.x, A1.x, A2.x, A3.x, B0.x, B1.x);  // Ah*Bh
                mma_tf32(acc[m][t], A0.x, A1.x, A2.x, A3.x, B0.y, B1.y);  // Ah*Bl
                mma_tf32(acc[m][t], A0.y, A1.y, A2.y, A3.y, B0.x, B1.x);  // Al*Bh
            }
        }
    }

    // epilogue: product of 4 accs, B-term, reduce over 64 rows
    float val[4][2];
    {
        int r_loc0 = rowg*16 + lr;
        float2 mb0 = ((const float2*)MBp)[l*64 + r_loc0];
        float2 mb1 = ((const float2*)MBp)[l*64 + r_loc0 + 8];
        #pragma unroll
        for (int t = 0; t < 4; t++) {
            #pragma unroll
            for (int c = 0; c < 2; c++) {
                int col = hng*32 + t*8 + lc*2 + c;
                float bt0 = mb0.x * svB0[col] + mb0.y * svB1[col];
                float bt1 = mb1.x * svB0[col] + mb1.y * svB1[col];
                float p0 = acc[0][t][c]   * acc[1][t][c]   * acc[2][t][c]   * acc[3][t][c]   * bt0;
                float p1 = acc[0][t][c+2] * acc[1][t][c+2] * acc[2][t][c+2] * acc[3][t][c+2] * bt1;
                val[t][c] = p0 + p1;
            }
        }
    }
    #pragma unroll
    for (int t = 0; t < 4; t++)
        #pragma unroll
        for (int c = 0; c < 2; c++) {
            float v = val[t][c];
            v += __shfl_xor_sync(0xffffffffu, v, 4);
            v += __shfl_xor_sync(0xffffffffu, v, 8);
            v += __shfl_xor_sync(0xffffffffu, v, 16);
            val[t][c] = v;
        }
    if (lane < 4) {
        #pragma unroll
        for (int t = 0; t < 4; t++)
            #pragma unroll
            for (int c = 0; c < 2; c++)
                sRed[rowg*64 + hng*32 + t*8 + lane*2 + c] = val[t][c];
    }
    __syncthreads();
    if (tid < 64) {
        float s = sRed[tid] + sRed[64 + tid] + sRed[128 + tid] + sRed[192 + tid];
        g_outs[(dir*1024 + l)*256 + q*64 + tid] = s;
    }
}
#define SMEM_PRODM (2*64*PRODP*8 + 128*4 + 256*4)

// ---------------- kernel C1: combine dirs with C1/C2, boundary scaling ----------------
__global__ void k_comb()
{
    int idx = blockIdx.x * 256 + threadIdx.x;  // 128*1024
    int h = idx >> 10;
    int l = idx & 1023;
    const float* o0 = g_outs + l*256;
    const float* o1 = g_outs + 262144 + l*256;
    int t = h*2;
    float v = o0[t]*g_c1[t] + o0[t+1]*g_c1[t+1] + o1[t]*g_c2[t] + o1[t+1]*g_c2[t+1];
    int li = l >> 5, lj = l & 31;
    float f = 1.0f;
    if (li == 0) f *= 2.0f;
    if (lj == 0) f *= 2.0f;
    if (li == 0 && lj == 0) f *= 0.25f;
    g_kk[h*1024 + l] = v * f;
}

// ---------------- kernel C2: fold flips -> 63x63 correlation kernel ----------------
__global__ void k_keff()
{
    int dpi = threadIdx.x;   // 0..63 (63 = zero pad)
    int dqi = blockIdx.x;    // 0..62
    int c   = blockIdx.y;    // 0..31
    float v = 0.0f;
    if (dpi < 63) {
        int dp = dpi - 31, dq = dqi - 31;
        if (dp <= 0 && dq <= 0) v += g_kk[(c      )*1024 + (-dp)*32 + (-dq)];
        if (dp >= 0 && dq <= 0) v += g_kk[(c + 32 )*1024 + ( dp)*32 + (-dq)];
        if (dp <= 0 && dq >= 0) v += g_kk[(c + 64 )*1024 + (-dp)*32 + ( dq)];
        if (dp >= 0 && dq >= 0) v += g_kk[(c + 96 )*1024 + ( dp)*32 + ( dq)];
    }
    g_Kf[(c*63 + dqi)*64 + dpi] = v;
}

// ---------------- kernel X: transpose+pack x (b,i,j,c) -> (c,bp,i,j) b-pairs ----------------
__global__ void k_xt(const float* __restrict__ x)
{
    int idx = blockIdx.x * 256 + threadIdx.x;   // 524288
    int j  = idx & 63;
    int i  = (idx >> 6) & 63;
    int bp = (idx >> 12) & 3;
    int c  = idx >> 14;
    float v0 = x[(((2*bp    )*64 + i)*64 + j)*32 + c];
    float v1 = x[(((2*bp + 1)*64 + i)*64 + j)*32 + c];
    g_xt2[idx] = pack2(v0, v1);
}

// ---------------- kernel D: direct 63x63 correlation, b-pair packed f32x2 ----------------
__global__ __launch_bounds__(256, 2) void k_conv()
{
    extern __shared__ u64 smemC[];
    u64*   sX = smemC;                 // [84][128]
    float* sK = (float*)(smemC + 84*128);  // [63][64]

    int c  = blockIdx.x;
    int bp = blockIdx.y;
    int i0 = blockIdx.z * 16;

    int tid = threadIdx.x;
    const u64* xp = g_xt2 + (c*4 + bp)*4096;
    for (int idx = tid; idx < 84*128; idx += 256) {
        int r  = idx >> 7, cj = idx & 127;
        int gi = i0 - 31 + r, gj = cj - 31;
        u64 v = 0ull;
        if ((unsigned)gi < 64u && (unsigned)gj < 64u) v = xp[gi*64 + gj];
        sX[idx] = v;
    }
    const float* Kc = g_Kf + c*4032;
    for (int idx = tid; idx < 4032; idx += 256) sK[idx] = Kc[idx];
    __syncthreads();

    int j  = tid & 63;
    int ig = tid >> 6;       // 0..3
    int ib = ig * 4;
    u64 acc[4];
    #pragma unroll
    for (int r = 0; r < 4; r++) acc[r] = 0ull;

    for (int dqi = 0; dqi < 63; dqi++) {
        int col = j + dqi;
        u64 w[8];
        #pragma unroll
        for (int k = 0; k < 8; k++) w[k] = sX[(ib + k)*128 + col];
        const float* Krow = sK + dqi*64;
        #pragma unroll
        for (int c8 = 0; c8 < 8; c8++) {
            const float4* kp = (const float4*)(Krow + c8*8);
            float4 k03 = kp[0];
            float4 k47 = kp[1];
            u64 kv[8] = {dup_f(k03.x), dup_f(k03.y), dup_f(k03.z), dup_f(k03.w),
                         dup_f(k47.x), dup_f(k47.y), dup_f(k47.z), dup_f(k47.w)};
            #pragma unroll
            for (int u = 0; u < 8; u++) {
                #pragma unroll
                for (int r = 0; r < 4; r++)
                    acc[r] = fma2(kv[u], w[(u + r) & 7], acc[r]);
                w[u] = sX[(ib + c8*8 + u + 8)*128 + col];
            }
        }
    }

    u64* yp = g_yt2 + (c*4 + bp)*4096;
    #pragma unroll
    for (int r = 0; r < 4; r++)
        yp[(i0 + ib + r)*64 + j] = acc[r];
}

// ---------------- kernel E: out = y @ W^T + b ----------------
__global__ __launch_bounds__(256, 4) void k_out(const float* __restrict__ W,
                                                const float* __restrict__ bias,
                                                float* __restrict__ out)
{
    int ip = blockIdx.x;   // i pair 0..31
    int b  = blockIdx.y;   // 0..7
    __shared__ float ys[2*32*64];   // [ii][c][j]
    __shared__ float Wt[32*32];     // Wt[c][e]

    int tid = threadIdx.x;
    int bp = b >> 1, bl = b & 1;
    for (int idx = tid; idx < 4096; idx += 256) {
        int ii = idx >> 11;
        int cc = (idx >> 6) & 31;
        int jx = idx & 63;
        u64 t = g_yt2[((cc*4 + bp)*64 + ip*2 + ii)*64 + jx];
        ys[idx] = bl ? hi_f(t) : lo_f(t);
    }
    for (int idx = tid; idx < 1024; idx += 256) {
        int e = idx & 31, cc = idx >> 5;
        Wt[cc*32 + e] = W[e*32 + cc];
    }
    __syncthreads();

    int e0 = (tid & 7) * 4;
    int j0 = (tid >> 3) * 2;
    float acc[2][2][4];
    #pragma unroll
    for (int ii = 0; ii < 2; ii++)
        #pragma unroll
        for (int jj = 0; jj < 2; jj++)
            #pragma unroll
            for (int k = 0; k < 4; k++) acc[ii][jj][k] = bias[e0 + k];

    for (int cc = 0; cc < 32; cc++) {
        float yv[2][2];
        #pragma unroll
        for (int ii = 0; ii < 2; ii++)
            #pragma unroll
            for (int jj = 0; jj < 2; jj++) yv[ii][jj] = ys[ii*2048 + cc*64 + j0 + jj];
        float wv[4];
        #pragma unroll
        for (int k = 0; k < 4; k++) wv[k] = Wt[cc*32 + e0 + k];
        #pragma unroll
        for (int ii = 0; ii < 2; ii++)
            #pragma unroll
            for (int jj = 0; jj < 2; jj++)
                #pragma unroll
                for (int k = 0; k < 4; k++)
                    acc[ii][jj][k] = fmaf(yv[ii][jj], wv[k], acc[ii][jj][k]);
    }

    #pragma unroll
    for (int ii = 0; ii < 2; ii++)
        #pragma unroll
        for (int jj = 0; jj < 2; jj++) {
            float* op = out + ((size_t)((b*64 + ip*2 + ii)*64 + j0 + jj))*32 + e0;
            #pragma unroll
            for (int k = 0; k < 4; k++) op[k] = acc[ii][jj][k];
        }
}

// ---------------- launch ----------------
extern "C" void kernel_launch(void* const* d_in, const int* in_sizes, int n_in,
                              void* d_out, int out_size)
{
    const float* x    = (const float*)d_in[0];
    const float* Mh1  = (const float*)d_in[1];
    const float* Mh2  = (const float*)d_in[2];
    const float* Mh3  = (const float*)d_in[3];
    const float* Mh4  = (const float*)d_in[4];
    const float* MhB  = (const float*)d_in[5];
    const float* Mv1  = (const float*)d_in[6];
    const float* Mv2  = (const float*)d_in[7];
    const float* Mv3  = (const float*)d_in[8];
    const float* Mv4  = (const float*)d_in[9];
    const float* MvB  = (const float*)d_in[10];
    const float* A1   = (const float*)d_in[11];
    const float* A2   = (const float*)d_in[12];
    const float* A3   = (const float*)d_in[13];
    const float* A4   = (const float*)d_in[14];
    const float* B1   = (const float*)d_in[15];
    const float* B2   = (const float*)d_in[16];
    const float* C1   = (const float*)d_in[17];
    const float* C2   = (const float*)d_in[18];
    const float* W    = (const float*)d_in[19];
    const float* bias = (const float*)d_in[20];
    float* out = (float*)d_out;

    const int smemConv = 84*128*8 + 63*64*4;                // 102144
    cudaFuncSetAttribute(k_prod_m, cudaFuncAttributeMaxDynamicSharedMemorySize, SMEM_PRODM);
    cudaFuncSetAttribute(k_conv, cudaFuncAttributeMaxDynamicSharedMemorySize, smemConv);

    k_vec  <<<256, 256>>>(A1, A2, A3, A4, B1, B2, C1, C2);
    k_prod_m<<<dim3(4, 1024, 2), 256, SMEM_PRODM>>>(Mh1, Mh2, Mh3, Mh4, MhB,
                                                    Mv1, Mv2, Mv3, Mv4, MvB);
    k_comb <<<512, 256>>>();
    k_keff <<<dim3(63, 32), 64>>>();
    k_xt   <<<2048, 256>>>(x);
    k_conv <<<dim3(32, 4, 4), 256, smemConv>>>();
    k_out  <<<dim3(32, 8), 256>>>(W, bias, out);
}

// round 10
// speedup vs baseline: 1.9885x; 1.9885x over previous
#include <cuda_runtime.h>
#include <math.h>
#include <stdint.h>

#define SCALEF 0.70710678118654752440f
typedef unsigned long long u64;

// ---------------- f32x2 helpers ----------------
__device__ __forceinline__ u64 dup_f(float x){ u64 r; asm("mov.b64 %0,{%1,%1};" : "=l"(r) : "f"(x)); return r; }
__device__ __forceinline__ u64 pack2(float lo, float hi){ u64 r; asm("mov.b64 %0,{%1,%2};" : "=l"(r) : "f"(lo), "f"(hi)); return r; }
__device__ __forceinline__ u64 fma2(u64 a, u64 b, u64 c){ u64 d; asm("fma.rn.f32x2 %0,%1,%2,%3;" : "=l"(d) : "l"(a),"l"(b),"l"(c)); return d; }
__device__ __forceinline__ u64 mul2(u64 a, u64 b){ u64 d; asm("mul.rn.f32x2 %0,%1,%2;" : "=l"(d) : "l"(a),"l"(b)); return d; }
__device__ __forceinline__ u64 add2(u64 a, u64 b){ u64 d; asm("add.rn.f32x2 %0,%1,%2;" : "=l"(d) : "l"(a),"l"(b)); return d; }
__device__ __forceinline__ float lo_f(u64 x){ float a,b; asm("mov.b64 {%0,%1},%2;" : "=f"(a),"=f"(b) : "l"(x)); return a; }
__device__ __forceinline__ float hi_f(u64 x){ float a,b; asm("mov.b64 {%0,%1},%2;" : "=f"(a),"=f"(b) : "l"(x)); return b; }

// ---------------- scratch ----------------
__device__ float g_vec[4*64*256];      // a^v tables  [m][v][hn]
__device__ float g_vB[2*256];          // sigmoid(B1), sigmoid(B2)
__device__ float g_c1[256];
__device__ float g_c2[256];
__device__ float g_outs[2*1024*256];   // [dir][l][hn]
__device__ float g_kk[128*1024];       // conv kernel [h][l], boundary-scaled
__device__ float g_Kf[32*63*64];       // combined corr kernel [c][dqi][dpi pad64] (pad=0)
__device__ u64   g_xt2[32*4*64*64];    // x, b-pair packed: [c][bp][i][j]
__device__ u64   g_yt2[32*4*64*64];    // conv output, same packing

// ---------------- kernel A: build vec tables (parallel) ----------------
__global__ void k_vec(const float* __restrict__ A1, const float* __restrict__ A2,
                      const float* __restrict__ A3, const float* __restrict__ A4,
                      const float* __restrict__ B1, const float* __restrict__ B2,
                      const float* __restrict__ C1, const float* __restrict__ C2)
{
    int idx = blockIdx.x * 256 + threadIdx.x;   // 65536 = 4m * 64v * 256hn
    int t = idx & 255;
    int v = (idx >> 8) & 63;
    int m = idx >> 14;
    const float* As[4] = {A1, A2, A3, A4};
    float a = 1.0f / (1.0f + expf(-As[m][t]));
    float p = (v == 0) ? 1.0f : exp2f((float)v * log2f(a));
    g_vec[idx] = p;
    if (idx < 256) {
        g_vB[t]       = 1.0f / (1.0f + expf(-B1[t]));
        g_vB[256 + t] = 1.0f / (1.0f + expf(-B2[t]));
        g_c1[t] = C1[t] * SCALEF;
        g_c2[t] = C2[t] * SCALEF;
    }
}

// ---------------- kernel B: GEMM-product + segment reduction ----------------
// block = (l, dir, hh). outs[dir][l][hh*128 + :128] over sum_j of prod_m
// tile: 8j x 2 u64 hn per thread. M rows stored PRE-DUPLICATED in smem (u64 dup),
// read via warp-uniform LDS.128 broadcast -> zero pack MOVs in the hot loop.
// smem: sMd u64[64][66] (33792B) + sV2 u64[64][64] (32768B) + sRed u64[8][64] (4096B)
__global__ __launch_bounds__(256, 2) void k_prod(
    const float* __restrict__ M1, const float* __restrict__ M2,
    const float* __restrict__ M3, const float* __restrict__ M4,
    const float* __restrict__ MB,
    const float* __restrict__ N1, const float* __restrict__ N2,
    const float* __restrict__ N3, const float* __restrict__ N4,
    const float* __restrict__ NB)
{
    extern __shared__ u64 smemP[];
    u64* sMd  = smemP;                  // [64 v][66 j] dup-packed
    u64* sV2  = smemP + 64*66;          // [64 v][64 hn-pairs]
    u64* sRed = sV2 + 64*64;            // [8][64]

    int l   = blockIdx.x;
    int dir = blockIdx.y;
    int hh  = blockIdx.z;   // hn half: 0 or 1
    const float* Mlist[4];
    const float* MBp;
    if (dir == 0) { Mlist[0]=M1; Mlist[1]=M2; Mlist[2]=M3; Mlist[3]=M4; MBp=MB; }
    else          { Mlist[0]=N1; Mlist[1]=N2; Mlist[2]=N3; Mlist[3]=N4; MBp=NB; }

    int tid = threadIdx.x;
    int tj  = tid >> 5;     // warp -> j group (uniform within warp)
    int tt  = tid & 31;
    int j0  = tj * 8;
    int p0  = tt * 2;       // u64 index within 64-u64 half

    u64 prod[8][2];
    u64 acc[8][2];

    for (int m = 0; m < 4; m++) {
        __syncthreads();
        const float* Mg = Mlist[m] + (size_t)l * 4096;
        for (int idx = tid; idx < 4096; idx += 256) {
            int j = idx >> 6, v = idx & 63;
            sMd[v*66 + j] = dup_f(Mg[idx]);
        }
        const u64* Vg = (const u64*)(g_vec + m*16384) + hh*64;
        for (int idx = tid; idx < 4096; idx += 256) {
            int v = idx >> 6, i = idx & 63;
            sV2[v*64 + i] = Vg[v*128 + i];
        }
        __syncthreads();

        #pragma unroll
        for (int jj = 0; jj < 8; jj++)
            #pragma unroll
            for (int k = 0; k < 2; k++) acc[jj][k] = 0ull;

        #pragma unroll 4
        for (int v = 0; v < 64; v++) {
            const u64* arow = sMd + v*66 + j0;
            ulonglong2 a01 = *(const ulonglong2*)(arow + 0);
            ulonglong2 a23 = *(const ulonglong2*)(arow + 2);
            ulonglong2 a45 = *(const ulonglong2*)(arow + 4);
            ulonglong2 a67 = *(const ulonglong2*)(arow + 6);
            ulonglong2 bp  = *(const ulonglong2*)(sV2 + v*64 + p0);
            u64 a8[8] = {a01.x,a01.y,a23.x,a23.y,a45.x,a45.y,a67.x,a67.y};
            u64 b2[2] = {bp.x, bp.y};
            #pragma unroll
            for (int jj = 0; jj < 8; jj++)
                #pragma unroll
                for (int k = 0; k < 2; k++)
                    acc[jj][k] = fma2(a8[jj], b2[k], acc[jj][k]);
        }

        if (m == 0) {
            #pragma unroll
            for (int jj = 0; jj < 8; jj++)
                #pragma unroll
                for (int k = 0; k < 2; k++) prod[jj][k] = acc[jj][k];
        } else {
            #pragma unroll
            for (int jj = 0; jj < 8; jj++)
                #pragma unroll
                for (int k = 0; k < 2; k++) prod[jj][k] = mul2(prod[jj][k], acc[jj][k]);
        }
    }

    // B-matrix term: *= MB[r,0]*sigB1[hn] + MB[r,1]*sigB2[hn]
    {
        const u64* vBu = (const u64*)g_vB;
        u64 vb0[2], vb1[2];
        #pragma unroll
        for (int k = 0; k < 2; k++) {
            vb0[k] = vBu[hh*64 + p0 + k];
            vb1[k] = vBu[128 + hh*64 + p0 + k];
        }
        #pragma unroll
        for (int jj = 0; jj < 8; jj++) {
            int r = l*64 + j0 + jj;
            u64 mbp = ((const u64*)MBp)[r];
            u64 mb0 = dup_f(lo_f(mbp)), mb1 = dup_f(hi_f(mbp));
            #pragma unroll
            for (int k = 0; k < 2; k++) {
                u64 t = fma2(mb1, vb1[k], mul2(mb0, vb0[k]));
                prod[jj][k] = mul2(prod[jj][k], t);
            }
        }
    }

    // reduce over j: 8 in-thread + 8 across warps
    #pragma unroll
    for (int k = 0; k < 2; k++) {
        u64 s = prod[0][k];
        #pragma unroll
        for (int jj = 1; jj < 8; jj++) s = add2(s, prod[jj][k]);
        sRed[tj*64 + p0 + k] = s;
    }
    __syncthreads();
    if (tid < 128) {
        const float* sRedF = (const float*)sRed;
        float s = 0.0f;
        #pragma unroll
        for (int w = 0; w < 8; w++) s += sRedF[w*128 + tid];
        g_outs[(dir*1024 + l)*256 + hh*128 + tid] = s;
    }
}
#define SMEM_PROD ((64*66 + 64*64 + 8*64) * 8)

// ---------------- kernel C1: combine dirs with C1/C2, boundary scaling ----------------
__global__ void k_comb()
{
    int idx = blockIdx.x * 256 + threadIdx.x;  // 128*1024
    int h = idx >> 10;
    int l = idx & 1023;
    const float* o0 = g_outs + l*256;
    const float* o1 = g_outs + 262144 + l*256;
    int t = h*2;
    float v = o0[t]*g_c1[t] + o0[t+1]*g_c1[t+1] + o1[t]*g_c2[t] + o1[t+1]*g_c2[t+1];
    int li = l >> 5, lj = l & 31;
    float f = 1.0f;
    if (li == 0) f *= 2.0f;
    if (lj == 0) f *= 2.0f;
    if (li == 0 && lj == 0) f *= 0.25f;
    g_kk[h*1024 + l] = v * f;
}

// ---------------- kernel C2: fold flips -> 63x63 correlation kernel ----------------
__global__ void k_keff()
{
    int dpi = threadIdx.x;   // 0..63 (63 = zero pad)
    int dqi = blockIdx.x;    // 0..62
    int c   = blockIdx.y;    // 0..31
    float v = 0.0f;
    if (dpi < 63) {
        int dp = dpi - 31, dq = dqi - 31;
        if (dp <= 0 && dq <= 0) v += g_kk[(c      )*1024 + (-dp)*32 + (-dq)];
        if (dp >= 0 && dq <= 0) v += g_kk[(c + 32 )*1024 + ( dp)*32 + (-dq)];
        if (dp <= 0 && dq >= 0) v += g_kk[(c + 64 )*1024 + (-dp)*32 + ( dq)];
        if (dp >= 0 && dq >= 0) v += g_kk[(c + 96 )*1024 + ( dp)*32 + ( dq)];
    }
    g_Kf[(c*63 + dqi)*64 + dpi] = v;
}

// ---------------- kernel X: transpose+pack x (b,i,j,c) -> (c,bp,i,j) b-pairs ----------------
__global__ void k_xt(const float* __restrict__ x)
{
    int idx = blockIdx.x * 256 + threadIdx.x;   // 524288
    int j  = idx & 63;
    int i  = (idx >> 6) & 63;
    int bp = (idx >> 12) & 3;
    int c  = idx >> 14;
    float v0 = x[(((2*bp    )*64 + i)*64 + j)*32 + c];
    float v1 = x[(((2*bp + 1)*64 + i)*64 + j)*32 + c];
    g_xt2[idx] = pack2(v0, v1);
}

// ---------------- kernel D: direct 63x63 correlation, b-pair packed f32x2 ----------------
// block: (c, bp, z) -> 32 output rows x 64 cols x 2 batches.
// 256 threads = 4 row-groups x 64 j; 8 rows/thread with a 16-deep register ring.
// smem: sX u64[94][128] (96256B) + sK float[63][64] (16128B) = 112384B -> 2 blocks/SM
__global__ __launch_bounds__(256, 2) void k_conv()
{
    extern __shared__ u64 smemC[];
    u64*   sX = smemC;                      // [94][128]
    float* sK = (float*)(smemC + 94*128);   // [63][64], col 63 of each row = 0 pad

    int c  = blockIdx.x;
    int bp = blockIdx.y;
    int i0 = blockIdx.z * 32;

    int tid = threadIdx.x;
    const u64* xp = g_xt2 + (c*4 + bp)*4096;
    for (int idx = tid; idx < 94*128; idx += 256) {
        int r  = idx >> 7, cj = idx & 127;
        int gi = i0 - 31 + r, gj = cj - 31;
        u64 v = 0ull;
        if ((unsigned)gi < 64u && (unsigned)gj < 64u) v = xp[gi*64 + gj];
        sX[idx] = v;
    }
    const float* Kc = g_Kf + c*4032;
    for (int idx = tid; idx < 4032; idx += 256) sK[idx] = Kc[idx];
    __syncthreads();

    int j  = tid & 63;
    int ig = tid >> 6;       // 0..3
    int ib = ig * 8;
    u64 acc[8];
    #pragma unroll
    for (int r = 0; r < 8; r++) acc[r] = 0ull;

    for (int dqi = 0; dqi < 63; dqi++) {
        int col = j + dqi;
        u64 w[16];
        #pragma unroll
        for (int k = 0; k < 16; k++) w[k] = sX[(ib + k)*128 + col];
        const float* Krow = sK + dqi*64;
        #pragma unroll
        for (int c8 = 0; c8 < 8; c8++) {
            const float4* kp = (const float4*)(Krow + c8*8);
            float4 k03 = kp[0];
            float4 k47 = kp[1];
            u64 kv[8] = {dup_f(k03.x), dup_f(k03.y), dup_f(k03.z), dup_f(k03.w),
                         dup_f(k47.x), dup_f(k47.y), dup_f(k47.z), dup_f(k47.w)};
            #pragma unroll
            for (int u = 0; u < 8; u++) {
                int dpi = c8*8 + u;      // 0..63; tap 63 has kv==0 (g_Kf pad)
                #pragma unroll
                for (int r = 0; r < 8; r++)
                    acc[r] = fma2(kv[u], w[(dpi + r) & 15], acc[r]);
                if (dpi < 54)
                    w[dpi & 15] = sX[(ib + dpi + 16)*128 + col];
            }
        }
    }

    u64* yp = g_yt2 + (c*4 + bp)*4096;
    #pragma unroll
    for (int r = 0; r < 8; r++)
        yp[(i0 + ib + r)*64 + j] = acc[r];
}
#define SMEM_CONV (94*128*8 + 63*64*4)

// ---------------- kernel E: out = y @ W^T + b ----------------
__global__ __launch_bounds__(256, 4) void k_out(const float* __restrict__ W,
                                                const float* __restrict__ bias,
                                                float* __restrict__ out)
{
    int ip = blockIdx.x;   // i pair 0..31
    int b  = blockIdx.y;   // 0..7
    __shared__ float ys[2*32*64];   // [ii][c][j]
    __shared__ float Wt[32*32];     // Wt[c][e]

    int tid = threadIdx.x;
    int bp = b >> 1, bl = b & 1;
    for (int idx = tid; idx < 4096; idx += 256) {
        int ii = idx >> 11;
        int cc = (idx >> 6) & 31;
        int jx = idx & 63;
        u64 t = g_yt2[((cc*4 + bp)*64 + ip*2 + ii)*64 + jx];
        ys[idx] = bl ? hi_f(t) : lo_f(t);
    }
    for (int idx = tid; idx < 1024; idx += 256) {
        int e = idx & 31, cc = idx >> 5;
        Wt[cc*32 + e] = W[e*32 + cc];
    }
    __syncthreads();

    int e0 = (tid & 7) * 4;
    int j0 = (tid >> 3) * 2;
    float acc[2][2][4];
    #pragma unroll
    for (int ii = 0; ii < 2; ii++)
        #pragma unroll
        for (int jj = 0; jj < 2; jj++)
            #pragma unroll
            for (int k = 0; k < 4; k++) acc[ii][jj][k] = bias[e0 + k];

    for (int cc = 0; cc < 32; cc++) {
        float yv[2][2];
        #pragma unroll
        for (int ii = 0; ii < 2; ii++)
            #pragma unroll
            for (int jj = 0; jj < 2; jj++) yv[ii][jj] = ys[ii*2048 + cc*64 + j0 + jj];
        float wv[4];
        #pragma unroll
        for (int k = 0; k < 4; k++) wv[k] = Wt[cc*32 + e0 + k];
        #pragma unroll
        for (int ii = 0; ii < 2; ii++)
            #pragma unroll
            for (int jj = 0; jj < 2; jj++)
                #pragma unroll
                for (int k = 0; k < 4; k++)
                    acc[ii][jj][k] = fmaf(yv[ii][jj], wv[k], acc[ii][jj][k]);
    }

    #pragma unroll
    for (int ii = 0; ii < 2; ii++)
        #pragma unroll
        for (int jj = 0; jj < 2; jj++) {
            float* op = out + ((size_t)((b*64 + ip*2 + ii)*64 + j0 + jj))*32 + e0;
            #pragma unroll
            for (int k = 0; k < 4; k++) op[k] = acc[ii][jj][k];
        }
}

// ---------------- launch ----------------
extern "C" void kernel_launch(void* const* d_in, const int* in_sizes, int n_in,
                              void* d_out, int out_size)
{
    const float* x    = (const float*)d_in[0];
    const float* Mh1  = (const float*)d_in[1];
    const float* Mh2  = (const float*)d_in[2];
    const float* Mh3  = (const float*)d_in[3];
    const float* Mh4  = (const float*)d_in[4];
    const float* MhB  = (const float*)d_in[5];
    const float* Mv1  = (const float*)d_in[6];
    const float* Mv2  = (const float*)d_in[7];
    const float* Mv3  = (const float*)d_in[8];
    const float* Mv4  = (const float*)d_in[9];
    const float* MvB  = (const float*)d_in[10];
    const float* A1   = (const float*)d_in[11];
    const float* A2   = (const float*)d_in[12];
    const float* A3   = (const float*)d_in[13];
    const float* A4   = (const float*)d_in[14];
    const float* B1   = (const float*)d_in[15];
    const float* B2   = (const float*)d_in[16];
    const float* C1   = (const float*)d_in[17];
    const float* C2   = (const float*)d_in[18];
    const float* W    = (const float*)d_in[19];
    const float* bias = (const float*)d_in[20];
    float* out = (float*)d_out;

    cudaFuncSetAttribute(k_prod, cudaFuncAttributeMaxDynamicSharedMemorySize, SMEM_PROD);
    cudaFuncSetAttribute(k_conv, cudaFuncAttributeMaxDynamicSharedMemorySize, SMEM_CONV);

    k_vec <<<256, 256>>>(A1, A2, A3, A4, B1, B2, C1, C2);
    k_prod<<<dim3(1024, 2, 2), 256, SMEM_PROD>>>(Mh1, Mh2, Mh3, Mh4, MhB,
                                                 Mv1, Mv2, Mv3, Mv4, MvB);
    k_comb<<<512, 256>>>();
    k_keff<<<dim3(63, 32), 64>>>();
    k_xt  <<<2048, 256>>>(x);
    k_conv<<<dim3(32, 4, 2), 256, SMEM_CONV>>>();
    k_out <<<dim3(32, 8), 256>>>(W, bias, out);
}

// round 13
// speedup vs baseline: 2.0989x; 1.0555x over previous
#include <cuda_runtime.h>
#include <math.h>
#include <stdint.h>

#define SCALEF 0.70710678118654752440f
typedef unsigned long long u64;

// ---------------- f32x2 helpers ----------------
__device__ __forceinline__ u64 dup_f(float x){ u64 r; asm("mov.b64 %0,{%1,%1};" : "=l"(r) : "f"(x)); return r; }
__device__ __forceinline__ u64 pack2(float lo, float hi){ u64 r; asm("mov.b64 %0,{%1,%2};" : "=l"(r) : "f"(lo), "f"(hi)); return r; }
__device__ __forceinline__ u64 fma2(u64 a, u64 b, u64 c){ u64 d; asm("fma.rn.f32x2 %0,%1,%2,%3;" : "=l"(d) : "l"(a),"l"(b),"l"(c)); return d; }
__device__ __forceinline__ u64 mul2(u64 a, u64 b){ u64 d; asm("mul.rn.f32x2 %0,%1,%2;" : "=l"(d) : "l"(a),"l"(b)); return d; }
__device__ __forceinline__ u64 add2(u64 a, u64 b){ u64 d; asm("add.rn.f32x2 %0,%1,%2;" : "=l"(d) : "l"(a),"l"(b)); return d; }
__device__ __forceinline__ float lo_f(u64 x){ float a,b; asm("mov.b64 {%0,%1},%2;" : "=f"(a),"=f"(b) : "l"(x)); return a; }
__device__ __forceinline__ float hi_f(u64 x){ float a,b; asm("mov.b64 {%0,%1},%2;" : "=f"(a),"=f"(b) : "l"(x)); return b; }

// ---------------- scratch ----------------
__device__ float g_vec[4*64*256];      // a^v tables  [m][v][hn]
__device__ float g_vB[2*256];          // sigmoid(B1), sigmoid(B2)
__device__ float g_c1[256];
__device__ float g_c2[256];
__device__ float g_outs[2*1024*256];   // [dir][l][hn]
__device__ float g_kk[128*1024];       // conv kernel [h][l], boundary-scaled
__device__ float g_Kf[32*63*64];       // combined corr kernel [c][dqi][dpi pad64]
__device__ u64   g_xt2[32*4*64*64];    // x, b-pair packed: [c][bp][i][j]
__device__ u64   g_yt2[32*4*64*64];    // conv output, same packing

// ---------------- kernel A: build vec tables (parallel) ----------------
__global__ void k_vec(const float* __restrict__ A1, const float* __restrict__ A2,
                      const float* __restrict__ A3, const float* __restrict__ A4,
                      const float* __restrict__ B1, const float* __restrict__ B2,
                      const float* __restrict__ C1, const float* __restrict__ C2)
{
    int idx = blockIdx.x * 256 + threadIdx.x;   // 65536 = 4m * 64v * 256hn
    int t = idx & 255;
    int v = (idx >> 8) & 63;
    int m = idx >> 14;
    const float* As[4] = {A1, A2, A3, A4};
    float a = 1.0f / (1.0f + expf(-As[m][t]));
    float p = (v == 0) ? 1.0f : exp2f((float)v * log2f(a));
    g_vec[idx] = p;
    if (idx < 256) {
        g_vB[t]       = 1.0f / (1.0f + expf(-B1[t]));
        g_vB[256 + t] = 1.0f / (1.0f + expf(-B2[t]));
        g_c1[t] = C1[t] * SCALEF;
        g_c2[t] = C2[t] * SCALEF;
    }
}

// ---------------- kernel B: GEMM-product + segment reduction (j-pair f32x2) ----------------
// block = (l, dir, hh). outs[dir][l][hh*128 + :128] = sum_j prod_m (M_m[l*64+j,:] . vec_m[:,hn])
// Thread tile: 4 j-pairs (8 j) x 4 hn. A pairs are natural u64 loads from sM[v][j]
// (warp-uniform broadcast LDS.128, zero pack MOVs); B needs 4 dup MOVs.
// Inner loop: 3 LDS + 4 MOV + 16 FFMA2 = 23 issues / 16 fma2.
// smem: sM float[64][68] (17408B) + sV float[64][128] (32768B) + sRed float[8][128] (4096B)
__global__ __launch_bounds__(256, 2) void k_prod(
    const float* __restrict__ M1, const float* __restrict__ M2,
    const float* __restrict__ M3, const float* __restrict__ M4,
    const float* __restrict__ MB,
    const float* __restrict__ N1, const float* __restrict__ N2,
    const float* __restrict__ N3, const float* __restrict__ N4,
    const float* __restrict__ NB)
{
    extern __shared__ float smemF[];
    float* sM   = smemF;                 // [64 v][68 j]
    float* sV   = smemF + 64*68;         // [64 v][128 hn]  (hh half)
    float* sRed = sV + 64*128;           // [8][128]

    int l   = blockIdx.x;
    int dir = blockIdx.y;
    int hh  = blockIdx.z;   // hn half: 0 or 1
    const float* Mlist[4];
    const float* MBp;
    if (dir == 0) { Mlist[0]=M1; Mlist[1]=M2; Mlist[2]=M3; Mlist[3]=M4; MBp=MB; }
    else          { Mlist[0]=N1; Mlist[1]=N2; Mlist[2]=N3; Mlist[3]=N4; MBp=NB; }

    int tid = threadIdx.x;
    int tj  = tid >> 5;     // warp -> j group (uniform within warp)
    int tt  = tid & 31;
    int j0  = tj * 8;
    int h0  = tt * 4;       // hn offset within 128-half

    u64 prod[4][4];         // [j-pair][hn]
    u64 acc[4][4];

    for (int m = 0; m < 4; m++) {
        __syncthreads();
        const float* Mg = Mlist[m] + (size_t)l * 4096;
        for (int idx = tid; idx < 4096; idx += 256) {
            int j = idx >> 6, v = idx & 63;
            sM[v*68 + j] = Mg[idx];
        }
        // sV[v][i] = g_vec[m][v][hh*128 + i]  (u64 copies — proven access pattern)
        {
            const u64* src = (const u64*)(g_vec + m*16384) + hh*64;
            u64* dst = (u64*)sV;
            for (int idx = tid; idx < 4096; idx += 256) {
                int v = idx >> 6, i2 = idx & 63;
                dst[v*64 + i2] = src[v*128 + i2];
            }
        }
        __syncthreads();

        #pragma unroll
        for (int jp = 0; jp < 4; jp++)
            #pragma unroll
            for (int h = 0; h < 4; h++) acc[jp][h] = 0ull;

        #pragma unroll 4
        for (int v = 0; v < 64; v++) {
            const u64* ap = (const u64*)(sM + v*68 + j0);
            ulonglong2 a01 = *(const ulonglong2*)(ap);
            ulonglong2 a23 = *(const ulonglong2*)(ap + 2);
            float4 bv = *(const float4*)(sV + v*128 + h0);
            u64 a4[4] = {a01.x, a01.y, a23.x, a23.y};
            u64 b4[4] = {dup_f(bv.x), dup_f(bv.y), dup_f(bv.z), dup_f(bv.w)};
            #pragma unroll
            for (int jp = 0; jp < 4; jp++)
                #pragma unroll
                for (int h = 0; h < 4; h++)
                    acc[jp][h] = fma2(a4[jp], b4[h], acc[jp][h]);
        }

        if (m == 0) {
            #pragma unroll
            for (int jp = 0; jp < 4; jp++)
                #pragma unroll
                for (int h = 0; h < 4; h++) prod[jp][h] = acc[jp][h];
        } else {
            #pragma unroll
            for (int jp = 0; jp < 4; jp++)
                #pragma unroll
                for (int h = 0; h < 4; h++) prod[jp][h] = mul2(prod[jp][h], acc[jp][h]);
        }
    }

    // B-matrix term: *= MB[r,0]*sigB1[hn] + MB[r,1]*sigB2[hn]
    {
        float vb0[4], vb1[4];
        #pragma unroll
        for (int h = 0; h < 4; h++) {
            int hn = hh*128 + h0 + h;
            vb0[h] = g_vB[hn];
            vb1[h] = g_vB[256 + hn];
        }
        const u64* MBu = (const u64*)MBp;
        #pragma unroll
        for (int jp = 0; jp < 4; jp++) {
            int r0 = l*64 + j0 + 2*jp;
            u64 m0 = MBu[r0];       // (MB[r0,0], MB[r0,1])
            u64 m1 = MBu[r0 + 1];   // (MB[r1,0], MB[r1,1])
            u64 mbx = pack2(lo_f(m0), lo_f(m1));   // MB[.,0] pair over (j0,j1)
            u64 mby = pack2(hi_f(m0), hi_f(m1));   // MB[.,1] pair
            #pragma unroll
            for (int h = 0; h < 4; h++) {
                u64 bt = fma2(mby, dup_f(vb1[h]), mul2(mbx, dup_f(vb0[h])));
                prod[jp][h] = mul2(prod[jp][h], bt);
            }
        }
    }

    // reduce over j: 4 pair-adds in-thread + lane-pair collapse + 8 warps via smem
    {
        #pragma unroll
        for (int h = 0; h < 4; h++) {
            u64 s = add2(add2(prod[0][h], prod[1][h]), add2(prod[2][h], prod[3][h]));
            sRed[tj*128 + h0 + h] = lo_f(s) + hi_f(s);
        }
    }
    __syncthreads();
    if (tid < 128) {
        float s = 0.0f;
        #pragma unroll
        for (int w = 0; w < 8; w++) s += sRed[w*128 + tid];
        g_outs[(dir*1024 + l)*256 + hh*128 + tid] = s;
    }
}
#define SMEM_PROD ((64*68 + 64*128 + 8*128) * 4)

// ---------------- kernel C1: combine dirs with C1/C2, boundary scaling ----------------
__global__ void k_comb()
{
    int idx = blockIdx.x * 256 + threadIdx.x;  // 128*1024
    int h = idx >> 10;
    int l = idx & 1023;
    const float* o0 = g_outs + l*256;
    const float* o1 = g_outs + 262144 + l*256;
    int t = h*2;
    float v = o0[t]*g_c1[t] + o0[t+1]*g_c1[t+1] + o1[t]*g_c2[t] + o1[t+1]*g_c2[t+1];
    int li = l >> 5, lj = l & 31;
    float f = 1.0f;
    if (li == 0) f *= 2.0f;
    if (lj == 0) f *= 2.0f;
    if (li == 0 && lj == 0) f *= 0.25f;
    g_kk[h*1024 + l] = v * f;
}

// ---------------- kernel C2: fold flips -> 63x63 correlation kernel ----------------
__global__ void k_keff()
{
    int dpi = threadIdx.x;   // 0..63 (63 = zero pad)
    int dqi = blockIdx.x;    // 0..62
    int c   = blockIdx.y;    // 0..31
    float v = 0.0f;
    if (dpi < 63) {
        int dp = dpi - 31, dq = dqi - 31;
        if (dp <= 0 && dq <= 0) v += g_kk[(c      )*1024 + (-dp)*32 + (-dq)];
        if (dp >= 0 && dq <= 0) v += g_kk[(c + 32 )*1024 + ( dp)*32 + (-dq)];
        if (dp <= 0 && dq >= 0) v += g_kk[(c + 64 )*1024 + (-dp)*32 + ( dq)];
        if (dp >= 0 && dq >= 0) v += g_kk[(c + 96 )*1024 + ( dp)*32 + ( dq)];
    }
    g_Kf[(c*63 + dqi)*64 + dpi] = v;
}

// ---------------- kernel X: transpose+pack x (b,i,j,c) -> (c,bp,i,j) b-pairs ----------------
__global__ void k_xt(const float* __restrict__ x)
{
    int idx = blockIdx.x * 256 + threadIdx.x;   // 524288
    int j  = idx & 63;
    int i  = (idx >> 6) & 63;
    int bp = (idx >> 12) & 3;
    int c  = idx >> 14;
    float v0 = x[(((2*bp    )*64 + i)*64 + j)*32 + c];
    float v1 = x[(((2*bp + 1)*64 + i)*64 + j)*32 + c];
    g_xt2[idx] = pack2(v0, v1);
}

// ---------------- kernel D: direct 63x63 correlation, b-pair packed f32x2 (R3 form) ----------------
// block: (c, bp, iq) -> 16 output rows x 64 cols x 2 batches.
// smem: sX u64[84][128] (86016B) + sK float[63][64] (16128B) = 102144B -> 2 blocks/SM
__global__ __launch_bounds__(256, 2) void k_conv()
{
    extern __shared__ u64 smemC[];
    u64*   sX = smemC;                 // [84][128]
    float* sK = (float*)(smemC + 84*128);  // [63][64]

    int c  = blockIdx.x;
    int bp = blockIdx.y;
    int i0 = blockIdx.z * 16;

    int tid = threadIdx.x;
    const u64* xp = g_xt2 + (c*4 + bp)*4096;
    for (int idx = tid; idx < 84*128; idx += 256) {
        int r  = idx >> 7, cj = idx & 127;
        int gi = i0 - 31 + r, gj = cj - 31;
        u64 v = 0ull;
        if ((unsigned)gi < 64u && (unsigned)gj < 64u) v = xp[gi*64 + gj];
        sX[idx] = v;
    }
    const float* Kc = g_Kf + c*4032;
    for (int idx = tid; idx < 4032; idx += 256) sK[idx] = Kc[idx];
    __syncthreads();

    int j  = tid & 63;
    int ig = tid >> 6;       // 0..3
    int ib = ig * 4;
    u64 acc[4];
    #pragma unroll
    for (int r = 0; r < 4; r++) acc[r] = 0ull;

    for (int dqi = 0; dqi < 63; dqi++) {
        int col = j + dqi;
        u64 w[8];
        #pragma unroll
        for (int k = 0; k < 8; k++) w[k] = sX[(ib + k)*128 + col];
        const float* Krow = sK + dqi*64;
        #pragma unroll
        for (int c8 = 0; c8 < 8; c8++) {
            const float4* kp = (const float4*)(Krow + c8*8);
            float4 k03 = kp[0];
            float4 k47 = kp[1];
            u64 kv[8] = {dup_f(k03.x), dup_f(k03.y), dup_f(k03.z), dup_f(k03.w),
                         dup_f(k47.x), dup_f(k47.y), dup_f(k47.z), dup_f(k47.w)};
            #pragma unroll
            for (int u = 0; u < 8; u++) {
                #pragma unroll
                for (int r = 0; r < 4; r++)
                    acc[r] = fma2(kv[u], w[(u + r) & 7], acc[r]);
                w[u] = sX[(ib + c8*8 + u + 8)*128 + col];
            }
        }
    }

    u64* yp = g_yt2 + (c*4 + bp)*4096;
    #pragma unroll
    for (int r = 0; r < 4; r++)
        yp[(i0 + ib + r)*64 + j] = acc[r];
}
#define SMEM_CONV (84*128*8 + 63*64*4)

// ---------------- kernel E: out = y @ W^T + b ----------------
__global__ __launch_bounds__(256, 4) void k_out(const float* __restrict__ W,
                                                const float* __restrict__ bias,
                                                float* __restrict__ out)
{
    int ip = blockIdx.x;   // i pair 0..31
    int b  = blockIdx.y;   // 0..7
    __shared__ float ys[2*32*64];   // [ii][c][j]
    __shared__ float Wt[32*32];     // Wt[c][e]

    int tid = threadIdx.x;
    int bp = b >> 1, bl = b & 1;
    for (int idx = tid; idx < 4096; idx += 256) {
        int ii = idx >> 11;
        int cc = (idx >> 6) & 31;
        int jx = idx & 63;
        u64 t = g_yt2[((cc*4 + bp)*64 + ip*2 + ii)*64 + jx];
        ys[idx] = bl ? hi_f(t) : lo_f(t);
    }
    for (int idx = tid; idx < 1024; idx += 256) {
        int e = idx & 31, cc = idx >> 5;
        Wt[cc*32 + e] = W[e*32 + cc];
    }
    __syncthreads();

    int e0 = (tid & 7) * 4;
    int j0 = (tid >> 3) * 2;
    float acc[2][2][4];
    #pragma unroll
    for (int ii = 0; ii < 2; ii++)
        #pragma unroll
        for (int jj = 0; jj < 2; jj++)
            #pragma unroll
            for (int k = 0; k < 4; k++) acc[ii][jj][k] = bias[e0 + k];

    for (int cc = 0; cc < 32; cc++) {
        float yv[2][2];
        #pragma unroll
        for (int ii = 0; ii < 2; ii++)
            #pragma unroll
            for (int jj = 0; jj < 2; jj++) yv[ii][jj] = ys[ii*2048 + cc*64 + j0 + jj];
        float wv[4];
        #pragma unroll
        for (int k = 0; k < 4; k++) wv[k] = Wt[cc*32 + e0 + k];
        #pragma unroll
        for (int ii = 0; ii < 2; ii++)
            #pragma unroll
            for (int jj = 0; jj < 2; jj++)
                #pragma unroll
                for (int k = 0; k < 4; k++)
                    acc[ii][jj][k] = fmaf(yv[ii][jj], wv[k], acc[ii][jj][k]);
    }

    #pragma unroll
    for (int ii = 0; ii < 2; ii++)
        #pragma unroll
        for (int jj = 0; jj < 2; jj++) {
            float* op = out + ((size_t)((b*64 + ip*2 + ii)*64 + j0 + jj))*32 + e0;
            #pragma unroll
            for (int k = 0; k < 4; k++) op[k] = acc[ii][jj][k];
        }
}

// ---------------- launch ----------------
extern "C" void kernel_launch(void* const* d_in, const int* in_sizes, int n_in,
                              void* d_out, int out_size)
{
    const float* x    = (const float*)d_in[0];
    const float* Mh1  = (const float*)d_in[1];
    const float* Mh2  = (const float*)d_in[2];
    const float* Mh3  = (const float*)d_in[3];
    const float* Mh4  = (const float*)d_in[4];
    const float* MhB  = (const float*)d_in[5];
    const float* Mv1  = (const float*)d_in[6];
    const float* Mv2  = (const float*)d_in[7];
    const float* Mv3  = (const float*)d_in[8];
    const float* Mv4  = (const float*)d_in[9];
    const float* MvB  = (const float*)d_in[10];
    const float* A1   = (const float*)d_in[11];
    const float* A2   = (const float*)d_in[12];
    const float* A3   = (const float*)d_in[13];
    const float* A4   = (const float*)d_in[14];
    const float* B1   = (const float*)d_in[15];
    const float* B2   = (const float*)d_in[16];
    const float* C1   = (const float*)d_in[17];
    const float* C2   = (const float*)d_in[18];
    const float* W    = (const float*)d_in[19];
    const float* bias = (const float*)d_in[20];
    float* out = (float*)d_out;

    cudaFuncSetAttribute(k_prod, cudaFuncAttributeMaxDynamicSharedMemorySize, SMEM_PROD);
    cudaFuncSetAttribute(k_conv, cudaFuncAttributeMaxDynamicSharedMemorySize, SMEM_CONV);

    k_vec <<<256, 256>>>(A1, A2, A3, A4, B1, B2, C1, C2);
    k_prod<<<dim3(1024, 2, 2), 256, SMEM_PROD>>>(Mh1, Mh2, Mh3, Mh4, MhB,
                                                 Mv1, Mv2, Mv3, Mv4, MvB);
    k_comb<<<512, 256>>>();
    k_keff<<<dim3(63, 32), 64>>>();
    k_xt  <<<2048, 256>>>(x);
    k_conv<<<dim3(32, 4, 4), 256, SMEM_CONV>>>();
    k_out <<<dim3(32, 8), 256>>>(W, bias, out);
}

// round 16
// speedup vs baseline: 2.2836x; 1.0880x over previous
#include <cuda_runtime.h>
#include <math.h>
#include <stdint.h>

#define SCALEF 0.70710678118654752440f
typedef unsigned long long u64;

// ---------------- f32x2 helpers ----------------
__device__ __forceinline__ u64 dup_f(float x){ u64 r; asm("mov.b64 %0,{%1,%1};" : "=l"(r) : "f"(x)); return r; }
__device__ __forceinline__ u64 pack2(float lo, float hi){ u64 r; asm("mov.b64 %0,{%1,%2};" : "=l"(r) : "f"(lo), "f"(hi)); return r; }
__device__ __forceinline__ u64 fma2(u64 a, u64 b, u64 c){ u64 d; asm("fma.rn.f32x2 %0,%1,%2,%3;" : "=l"(d) : "l"(a),"l"(b),"l"(c)); return d; }
__device__ __forceinline__ u64 mul2(u64 a, u64 b){ u64 d; asm("mul.rn.f32x2 %0,%1,%2;" : "=l"(d) : "l"(a),"l"(b)); return d; }
__device__ __forceinline__ u64 add2(u64 a, u64 b){ u64 d; asm("add.rn.f32x2 %0,%1,%2;" : "=l"(d) : "l"(a),"l"(b)); return d; }
__device__ __forceinline__ float lo_f(u64 x){ float a,b; asm("mov.b64 {%0,%1},%2;" : "=f"(a),"=f"(b) : "l"(x)); return a; }
__device__ __forceinline__ float hi_f(u64 x){ float a,b; asm("mov.b64 {%0,%1},%2;" : "=f"(a),"=f"(b) : "l"(x)); return b; }

// ---------------- scratch ----------------
__device__ float g_vec[4*64*256];      // a^v tables  [m][v][hn]
__device__ float g_vB[2*256];          // sigmoid(B1), sigmoid(B2)
__device__ float g_c1[256];
__device__ float g_c2[256];
__device__ float g_outs[2*1024*256];   // [dir][l][hn]
__device__ float g_kk[128*1024];       // conv kernel [h][l], boundary-scaled
__device__ float g_Kf[32*63*64];       // combined corr kernel [c][dqi][dpi pad64]
__device__ u64   g_xt2[32*4*64*64];    // x, b-pair packed: [c][bp][i][j]
__device__ u64   g_yt2[32*4*64*64];    // conv output, same packing

// ---------------- kernel A: build vec tables (parallel) ----------------
__global__ void k_vec(const float* __restrict__ A1, const float* __restrict__ A2,
                      const float* __restrict__ A3, const float* __restrict__ A4,
                      const float* __restrict__ B1, const float* __restrict__ B2,
                      const float* __restrict__ C1, const float* __restrict__ C2)
{
    int idx = blockIdx.x * 256 + threadIdx.x;   // 65536 = 4m * 64v * 256hn
    int t = idx & 255;
    int v = (idx >> 8) & 63;
    int m = idx >> 14;
    const float* As[4] = {A1, A2, A3, A4};
    float a = 1.0f / (1.0f + expf(-As[m][t]));
    float p = (v == 0) ? 1.0f : exp2f((float)v * log2f(a));
    g_vec[idx] = p;
    if (idx < 256) {
        g_vB[t]       = 1.0f / (1.0f + expf(-B1[t]));
        g_vB[256 + t] = 1.0f / (1.0f + expf(-B2[t]));
        g_c1[t] = C1[t] * SCALEF;
        g_c2[t] = C2[t] * SCALEF;
    }
}

// ---------------- kernel B: GEMM-product, double-buffered staging ----------------
// block x = l*2+hh (hh-paired blocks adjacent -> M L2 reuse), y = dir.
// Thread tile: 4 j-pairs (8 j) x 4 hn, f32x2 packed along j.
// Double-buffered smem, ONE sync per m; M[m+1] prefetched into 16 regs before
// compute(m) so its DRAM latency hides under ~1500 compute issues.
// Per-buffer floats: sM 64*68=4352, sV 64*64 u64 = 8192 floats -> 12544 floats.
#define PBUF 12544
#define PSRED (2*PBUF)
#define SMEM_PROD ((2*PBUF + 8*128) * 4)   // 104448 B
__global__ __launch_bounds__(256, 2) void k_prod(
    const float* __restrict__ M1, const float* __restrict__ M2,
    const float* __restrict__ M3, const float* __restrict__ M4,
    const float* __restrict__ MB,
    const float* __restrict__ N1, const float* __restrict__ N2,
    const float* __restrict__ N3, const float* __restrict__ N4,
    const float* __restrict__ NB)
{
    extern __shared__ float smemF[];
    float* sRed = smemF + PSRED;         // [8][128]

    int l   = blockIdx.x >> 1;
    int hh  = blockIdx.x & 1;   // hn half
    int dir = blockIdx.y;
    const float* Mlist[4];
    const float* MBp;
    if (dir == 0) { Mlist[0]=M1; Mlist[1]=M2; Mlist[2]=M3; Mlist[3]=M4; MBp=MB; }
    else          { Mlist[0]=N1; Mlist[1]=N2; Mlist[2]=N3; Mlist[3]=N4; MBp=NB; }

    int tid = threadIdx.x;
    int tj  = tid >> 5;     // warp -> j group (uniform within warp)
    int tt  = tid & 31;
    int j0  = tj * 8;
    int h0  = tt * 4;       // hn offset within 128-half

    u64 prod[4][4];         // [j-pair][hn]
    u64 acc[4][4];
    float rM[16];           // prefetch regs for next m's M tile

    // stage m=0 fully into buffer 0
    {
        float* sM0 = smemF;
        u64*   sV0 = (u64*)(smemF + 4352);
        const float* Mg = Mlist[0] + (size_t)l * 4096;
        #pragma unroll
        for (int i = 0; i < 16; i++) {
            int idx = tid + i*256;
            int j = idx >> 6, v = idx & 63;
            sM0[v*68 + j] = Mg[idx];
        }
        const u64* src = (const u64*)(g_vec) + hh*64;
        #pragma unroll
        for (int i = 0; i < 16; i++) {
            int idx = tid + i*256;
            int v = idx >> 6, i2 = idx & 63;
            sV0[v*64 + i2] = src[v*128 + i2];
        }
    }
    __syncthreads();

    for (int m = 0; m < 4; m++) {
        int cur = m & 1;
        float* sM = smemF + cur*PBUF;
        float* sV = smemF + cur*PBUF + 4352;

        // prefetch next m's M into registers (LDGs issued before compute)
        if (m < 3) {
            const float* Mg = Mlist[m+1] + (size_t)l * 4096;
            #pragma unroll
            for (int i = 0; i < 16; i++) rM[i] = Mg[tid + i*256];
        }

        #pragma unroll
        for (int jp = 0; jp < 4; jp++)
            #pragma unroll
            for (int h = 0; h < 4; h++) acc[jp][h] = 0ull;

        #pragma unroll 4
        for (int v = 0; v < 64; v++) {
            const u64* ap = (const u64*)(sM + v*68 + j0);
            ulonglong2 a01 = *(const ulonglong2*)(ap);
            ulonglong2 a23 = *(const ulonglong2*)(ap + 2);
            float4 bv = *(const float4*)(sV + v*128 + h0);
            u64 a4[4] = {a01.x, a01.y, a23.x, a23.y};
            u64 b4[4] = {dup_f(bv.x), dup_f(bv.y), dup_f(bv.z), dup_f(bv.w)};
            #pragma unroll
            for (int jp = 0; jp < 4; jp++)
                #pragma unroll
                for (int h = 0; h < 4; h++)
                    acc[jp][h] = fma2(a4[jp], b4[h], acc[jp][h]);
        }

        if (m == 0) {
            #pragma unroll
            for (int jp = 0; jp < 4; jp++)
                #pragma unroll
                for (int h = 0; h < 4; h++) prod[jp][h] = acc[jp][h];
        } else {
            #pragma unroll
            for (int jp = 0; jp < 4; jp++)
                #pragma unroll
                for (int h = 0; h < 4; h++) prod[jp][h] = mul2(prod[jp][h], acc[jp][h]);
        }

        // store prefetched M + stage vec (L2-hot) into the other buffer
        if (m < 3) {
            int nxt = cur ^ 1;
            float* sMn = smemF + nxt*PBUF;
            u64*   sVn = (u64*)(smemF + nxt*PBUF + 4352);
            #pragma unroll
            for (int i = 0; i < 16; i++) {
                int idx = tid + i*256;
                int j = idx >> 6, v = idx & 63;
                sMn[v*68 + j] = rM[i];
            }
            const u64* src = (const u64*)(g_vec + (m+1)*16384) + hh*64;
            #pragma unroll
            for (int i = 0; i < 16; i++) {
                int idx = tid + i*256;
                int v = idx >> 6, i2 = idx & 63;
                sVn[v*64 + i2] = src[v*128 + i2];
            }
        }
        __syncthreads();
    }

    // B-matrix term: *= MB[r,0]*sigB1[hn] + MB[r,1]*sigB2[hn]
    {
        float vb0[4], vb1[4];
        #pragma unroll
        for (int h = 0; h < 4; h++) {
            int hn = hh*128 + h0 + h;
            vb0[h] = g_vB[hn];
            vb1[h] = g_vB[256 + hn];
        }
        const u64* MBu = (const u64*)MBp;
        #pragma unroll
        for (int jp = 0; jp < 4; jp++) {
            int r0 = l*64 + j0 + 2*jp;
            u64 m0 = MBu[r0];       // (MB[r0,0], MB[r0,1])
            u64 m1 = MBu[r0 + 1];   // (MB[r1,0], MB[r1,1])
            u64 mbx = pack2(lo_f(m0), lo_f(m1));   // MB[.,0] pair over (j0,j1)
            u64 mby = pack2(hi_f(m0), hi_f(m1));   // MB[.,1] pair
            #pragma unroll
            for (int h = 0; h < 4; h++) {
                u64 bt = fma2(mby, dup_f(vb1[h]), mul2(mbx, dup_f(vb0[h])));
                prod[jp][h] = mul2(prod[jp][h], bt);
            }
        }
    }

    // reduce over j: 4 pair-adds in-thread + lane collapse + 8 warps via smem
    {
        #pragma unroll
        for (int h = 0; h < 4; h++) {
            u64 s = add2(add2(prod[0][h], prod[1][h]), add2(prod[2][h], prod[3][h]));
            sRed[tj*128 + h0 + h] = lo_f(s) + hi_f(s);
        }
    }
    __syncthreads();
    if (tid < 128) {
        float s = 0.0f;
        #pragma unroll
        for (int w = 0; w < 8; w++) s += sRed[w*128 + tid];
        g_outs[(dir*1024 + l)*256 + hh*128 + tid] = s;
    }
}

// ---------------- kernel C1: combine dirs with C1/C2, boundary scaling ----------------
__global__ void k_comb()
{
    int idx = blockIdx.x * 256 + threadIdx.x;  // 128*1024
    int h = idx >> 10;
    int l = idx & 1023;
    const float* o0 = g_outs + l*256;
    const float* o1 = g_outs + 262144 + l*256;
    int t = h*2;
    float v = o0[t]*g_c1[t] + o0[t+1]*g_c1[t+1] + o1[t]*g_c2[t] + o1[t+1]*g_c2[t+1];
    int li = l >> 5, lj = l & 31;
    float f = 1.0f;
    if (li == 0) f *= 2.0f;
    if (lj == 0) f *= 2.0f;
    if (li == 0 && lj == 0) f *= 0.25f;
    g_kk[h*1024 + l] = v * f;
}

// ---------------- kernel C2: fold flips -> 63x63 correlation kernel ----------------
__global__ void k_keff()
{
    int dpi = threadIdx.x;   // 0..63 (63 = zero pad)
    int dqi = blockIdx.x;    // 0..62
    int c   = blockIdx.y;    // 0..31
    float v = 0.0f;
    if (dpi < 63) {
        int dp = dpi - 31, dq = dqi - 31;
        if (dp <= 0 && dq <= 0) v += g_kk[(c      )*1024 + (-dp)*32 + (-dq)];
        if (dp >= 0 && dq <= 0) v += g_kk[(c + 32 )*1024 + ( dp)*32 + (-dq)];
        if (dp <= 0 && dq >= 0) v += g_kk[(c + 64 )*1024 + (-dp)*32 + ( dq)];
        if (dp >= 0 && dq >= 0) v += g_kk[(c + 96 )*1024 + ( dp)*32 + ( dq)];
    }
    g_Kf[(c*63 + dqi)*64 + dpi] = v;
}

// ---------------- kernel X: transpose+pack x (b,i,j,c) -> (c,bp,i,j) b-pairs ----------------
__global__ void k_xt(const float* __restrict__ x)
{
    int idx = blockIdx.x * 256 + threadIdx.x;   // 524288
    int j  = idx & 63;
    int i  = (idx >> 6) & 63;
    int bp = (idx >> 12) & 3;
    int c  = idx >> 14;
    float v0 = x[(((2*bp    )*64 + i)*64 + j)*32 + c];
    float v1 = x[(((2*bp + 1)*64 + i)*64 + j)*32 + c];
    g_xt2[idx] = pack2(v0, v1);
}

// ---------------- kernel D: direct 63x63 correlation, b-pair packed f32x2 (R3 form) ----------------
// block: (c, bp, iq) -> 16 output rows x 64 cols x 2 batches.
// smem: sX u64[84][128] (86016B) + sK float[63][64] (16128B) = 102144B -> 2 blocks/SM
__global__ __launch_bounds__(256, 2) void k_conv()
{
    extern __shared__ u64 smemC[];
    u64*   sX = smemC;                 // [84][128]
    float* sK = (float*)(smemC + 84*128);  // [63][64]

    int c  = blockIdx.x;
    int bp = blockIdx.y;
    int i0 = blockIdx.z * 16;

    int tid = threadIdx.x;
    const u64* xp = g_xt2 + (c*4 + bp)*4096;
    for (int idx = tid; idx < 84*128; idx += 256) {
        int r  = idx >> 7, cj = idx & 127;
        int gi = i0 - 31 + r, gj = cj - 31;
        u64 v = 0ull;
        if ((unsigned)gi < 64u && (unsigned)gj < 64u) v = xp[gi*64 + gj];
        sX[idx] = v;
    }
    const float* Kc = g_Kf + c*4032;
    for (int idx = tid; idx < 4032; idx += 256) sK[idx] = Kc[idx];
    __syncthreads();

    int j  = tid & 63;
    int ig = tid >> 6;       // 0..3
    int ib = ig * 4;
    u64 acc[4];
    #pragma unroll
    for (int r = 0; r < 4; r++) acc[r] = 0ull;

    for (int dqi = 0; dqi < 63; dqi++) {
        int col = j + dqi;
        u64 w[8];
        #pragma unroll
        for (int k = 0; k < 8; k++) w[k] = sX[(ib + k)*128 + col];
        const float* Krow = sK + dqi*64;
        #pragma unroll
        for (int c8 = 0; c8 < 8; c8++) {
            const float4* kp = (const float4*)(Krow + c8*8);
            float4 k03 = kp[0];
            float4 k47 = kp[1];
            u64 kv[8] = {dup_f(k03.x), dup_f(k03.y), dup_f(k03.z), dup_f(k03.w),
                         dup_f(k47.x), dup_f(k47.y), dup_f(k47.z), dup_f(k47.w)};
            #pragma unroll
            for (int u = 0; u < 8; u++) {
                #pragma unroll
                for (int r = 0; r < 4; r++)
                    acc[r] = fma2(kv[u], w[(u + r) & 7], acc[r]);
                w[u] = sX[(ib + c8*8 + u + 8)*128 + col];
            }
        }
    }

    u64* yp = g_yt2 + (c*4 + bp)*4096;
    #pragma unroll
    for (int r = 0; r < 4; r++)
        yp[(i0 + ib + r)*64 + j] = acc[r];
}
#define SMEM_CONV (84*128*8 + 63*64*4)

// ---------------- kernel E: out = y @ W^T + b ----------------
__global__ __launch_bounds__(256, 4) void k_out(const float* __restrict__ W,
                                                const float* __restrict__ bias,
                                                float* __restrict__ out)
{
    int ip = blockIdx.x;   // i pair 0..31
    int b  = blockIdx.y;   // 0..7
    __shared__ float ys[2*32*64];   // [ii][c][j]
    __shared__ float Wt[32*32];     // Wt[c][e]

    int tid = threadIdx.x;
    int bp = b >> 1, bl = b & 1;
    for (int idx = tid; idx < 4096; idx += 256) {
        int ii = idx >> 11;
        int cc = (idx >> 6) & 31;
        int jx = idx & 63;
        u64 t = g_yt2[((cc*4 + bp)*64 + ip*2 + ii)*64 + jx];
        ys[idx] = bl ? hi_f(t) : lo_f(t);
    }
    for (int idx = tid; idx < 1024; idx += 256) {
        int e = idx & 31, cc = idx >> 5;
        Wt[cc*32 + e] = W[e*32 + cc];
    }
    __syncthreads();

    int e0 = (tid & 7) * 4;
    int j0 = (tid >> 3) * 2;
    float acc[2][2][4];
    #pragma unroll
    for (int ii = 0; ii < 2; ii++)
        #pragma unroll
        for (int jj = 0; jj < 2; jj++)
            #pragma unroll
            for (int k = 0; k < 4; k++) acc[ii][jj][k] = bias[e0 + k];

    for (int cc = 0; cc < 32; cc++) {
        float yv[2][2];
        #pragma unroll
        for (int ii = 0; ii < 2; ii++)
            #pragma unroll
            for (int jj = 0; jj < 2; jj++) yv[ii][jj] = ys[ii*2048 + cc*64 + j0 + jj];
        float wv[4];
        #pragma unroll
        for (int k = 0; k < 4; k++) wv[k] = Wt[cc*32 + e0 + k];
        #pragma unroll
        for (int ii = 0; ii < 2; ii++)
            #pragma unroll
            for (int jj = 0; jj < 2; jj++)
                #pragma unroll
                for (int k = 0; k < 4; k++)
                    acc[ii][jj][k] = fmaf(yv[ii][jj], wv[k], acc[ii][jj][k]);
    }

    #pragma unroll
    for (int ii = 0; ii < 2; ii++)
        #pragma unroll
        for (int jj = 0; jj < 2; jj++) {
            float* op = out + ((size_t)((b*64 + ip*2 + ii)*64 + j0 + jj))*32 + e0;
            #pragma unroll
            for (int k = 0; k < 4; k++) op[k] = acc[ii][jj][k];
        }
}

// ---------------- launch ----------------
extern "C" void kernel_launch(void* const* d_in, const int* in_sizes, int n_in,
                              void* d_out, int out_size)
{
    const float* x    = (const float*)d_in[0];
    const float* Mh1  = (const float*)d_in[1];
    const float* Mh2  = (const float*)d_in[2];
    const float* Mh3  = (const float*)d_in[3];
    const float* Mh4  = (const float*)d_in[4];
    const float* MhB  = (const float*)d_in[5];
    const float* Mv1  = (const float*)d_in[6];
    const float* Mv2  = (const float*)d_in[7];
    const float* Mv3  = (const float*)d_in[8];
    const float* Mv4  = (const float*)d_in[9];
    const float* MvB  = (const float*)d_in[10];
    const float* A1   = (const float*)d_in[11];
    const float* A2   = (const float*)d_in[12];
    const float* A3   = (const float*)d_in[13];
    const float* A4   = (const float*)d_in[14];
    const float* B1   = (const float*)d_in[15];
    const float* B2   = (const float*)d_in[16];
    const float* C1   = (const float*)d_in[17];
    const float* C2   = (const float*)d_in[18];
    const float* W    = (const float*)d_in[19];
    const float* bias = (const float*)d_in[20];
    float* out = (float*)d_out;

    cudaFuncSetAttribute(k_prod, cudaFuncAttributeMaxDynamicSharedMemorySize, SMEM_PROD);
    cudaFuncSetAttribute(k_conv, cudaFuncAttributeMaxDynamicSharedMemorySize, SMEM_CONV);

    k_vec <<<256, 256>>>(A1, A2, A3, A4, B1, B2, C1, C2);
    k_prod<<<dim3(2048, 2), 256, SMEM_PROD>>>(Mh1, Mh2, Mh3, Mh4, MhB,
                                              Mv1, Mv2, Mv3, Mv4, MvB);
    k_comb<<<512, 256>>>();
    k_keff<<<dim3(63, 32), 64>>>();
    k_xt  <<<2048, 256>>>(x);
    k_conv<<<dim3(32, 4, 4), 256, SMEM_CONV>>>();
    k_out <<<dim3(32, 8), 256>>>(W, bias, out);
}